// round 11
// baseline (speedup 1.0000x reference)
#include <cuda_runtime.h>
#include <math.h>

// Hausdorff, D=H=W=20, V=8000, batch 2. Exact integer squared-EDT.
// ONE kernel, 80 blocks: block = (transform t, z-plane z0).
// Set-mask volume digested via coalesced LDG + __ballot_sync into a 250-word
// bitmap in SMEM (1 line + 1 ballot per warp-chunk); each thread extracts its
// (x,y) row's 20 bits with one funnel shift. z-pass O(1) (clz/ffs), y/x
// passes tree-min in SMEM. Tail: per-block atomicMax + 80-arrival counter.

#define INF_S 32000   // max legit squared distance = 3*19^2 = 1083
#define PAD   8

__device__ unsigned g_gmax[4 * PAD];   // per-transform max d2+1 (0 = none); zero-init
__device__ unsigned g_any[2 * PAD];    // any(mask A) per sample; zero-init
__device__ unsigned g_done = 0;

__global__ void __launch_bounds__(416, 1)
haus_plane(const float* __restrict__ predict,
           const float* __restrict__ targetp,
           float* __restrict__ out)
{
    __shared__ unsigned words[256];    // 250-word occupancy bitmap (flat v index)
    __shared__ int F1[400];
    __shared__ int F2[400];
    __shared__ int sred;
    __shared__ int sany;

    const int b  = blockIdx.x;         // t*20 + z0
    const int t  = b / 20, z0 = b - t * 20;
    const int n  = t >> 1,  m  = t & 1;
    const float* setSrc = (m ? targetp : predict) + n * 8000;
    const float* othSrc = (m ? predict : targetp) + n * 8000;
    const int tid  = threadIdx.x;
    const int lane = tid & 31, warp = tid >> 5;   // 13 full warps

    if (tid >= 250 && tid < 256) words[tid] = 0;  // guard words for funnelshift
    if (tid == 0) { sred = 0; sany = 0; }

    // early "other" load at own cell (latency overlapped with the sweep)
    float ov = 0.0f;
    if (tid < 400) ov = othSrc[tid * 20 + z0];

    // ---- coalesced sweep: 32 contiguous cells per warp-chunk -> ballot ----
    unsigned anybit = 0;
    for (int j = warp; j < 250; j += 13) {
        float v = setSrc[j * 32 + lane];           // 128B/warp, 1 line
        // jnp.round == round-half-even == rintf
        unsigned bal = __ballot_sync(0xffffffffu, rintf(v) != 0.0f);
        anybit |= bal;
        if (lane == 0) words[j] = bal;
    }
    if (lane == 0 && anybit) sany = 1;             // benign race
    __syncthreads();

    int x = 0, y = 0, oo = 0;
    if (tid < 400) {
        x = tid / 20; y = tid - x * 20;
        // extract this row's 20 occupancy bits [20*tid, 20*tid+20)
        int bitpos = tid * 20;
        unsigned w0 = words[bitpos >> 5];
        unsigned w1 = words[(bitpos >> 5) + 1];
        unsigned bits = __funnelshift_r(w0, w1, bitpos & 31) & 0xFFFFFu;

        // z-pass at fixed z0: nearest set bit, O(1)
        int dist = 100;
        unsigned lo = bits & ((2u << z0) - 1u);
        if (lo) dist = z0 - (31 - __clz(lo));
        unsigned hi = bits >> z0;
        if (hi) dist = min(dist, __ffs(hi) - 1);
        F1[tid] = (dist <= 19) ? dist * dist : INF_S;

        int s = (bits >> z0) & 1;
        oo = (rintf(ov) != 0.0f) & (s ^ 1);        // "other-only" point
    }
    __syncthreads();

    // ---- y-pass: F2(x,y) = min_yp F1(x,yp) + (y-yp)^2 (tree-min) ----
    if (tid < 400) {
        int c[20];
        const int base = x * 20;
        #pragma unroll
        for (int yp = 0; yp < 20; yp++) {
            int dy = y - yp;
            c[yp] = F1[base + yp] + dy * dy;
        }
        #pragma unroll
        for (int st = 1; st < 20; st <<= 1)
            #pragma unroll
            for (int i = 0; i + st < 20; i += (st << 1)) c[i] = min(c[i], c[i + st]);
        F2[tid] = c[0];
    }
    __syncthreads();

    // ---- x-pass + classification ----
    int enc = 0;                                   // best+1; 0 = none
    if (tid < 400) {
        int c[20];
        #pragma unroll
        for (int xp = 0; xp < 20; xp++) {
            int dx = x - xp;
            c[xp] = F2[xp * 20 + y] + dx * dx;
        }
        #pragma unroll
        for (int st = 1; st < 20; st <<= 1)
            #pragma unroll
            for (int i = 0; i + st < 20; i += (st << 1)) c[i] = min(c[i], c[i + st]);
        if (oo) enc = c[0] + 1;
    }
    enc = __reduce_max_sync(0xffffffffu, enc);
    if ((tid & 31) == 0 && enc) atomicMax(&sred, enc);
    __syncthreads();

    // ---- tail ----
    if (tid == 0) {
        if (sred) atomicMax(&g_gmax[t * PAD], (unsigned)sred);
        if (m == 0 && z0 == 0)                     // single writer per sample
            *(volatile unsigned*)&g_any[n * PAD] = (unsigned)sany;
        __threadfence();
        unsigned done = atomicAdd(&g_done, 1);
        if (done == 79) {
            __threadfence();
            volatile unsigned* vmax = (volatile unsigned*)g_gmax;
            volatile unsigned* vany = (volatile unsigned*)g_any;
            float sum = 0.0f;
            #pragma unroll
            for (int nn = 0; nn < 2; nn++) {
                int a2   = (int)vmax[(nn * 2 + 1) * PAD] - 1;  // A-only -> B (set=B)
                int b2   = (int)vmax[(nn * 2 + 0) * PAD] - 1;  // B-only -> A (set=A)
                int anyA = (int)vany[nn * PAD];
                float dA = 0.0f;
                if (a2 >= 0) dA = (a2 > 1083) ? 1e9f : sqrtf((float)a2) * 0.05f;
                float dB = 0.0f;
                if (b2 >= 0) dB = anyA ? ((b2 > 1083) ? 1e9f : sqrtf((float)b2) * 0.05f)
                                       : 999.0f;
                sum += fmaxf(dA, dB);
                vmax[(nn * 2 + 0) * PAD] = 0;
                vmax[(nn * 2 + 1) * PAD] = 0;
                vany[nn * PAD] = 0;
            }
            out[0] = sum * 0.5f;
            *(volatile unsigned*)&g_done = 0;      // restore static-init state
        }
    }
}

extern "C" void kernel_launch(void* const* d_in, const int* in_sizes, int n_in,
                              void* d_out, int out_size)
{
    const float* predict = (const float*)d_in[0];
    const float* targetp = (const float*)d_in[1];
    haus_plane<<<80, 416>>>(predict, targetp, (float*)d_out);
}

// round 12
// speedup vs baseline: 1.1633x; 1.1633x over previous
#include <cuda_runtime.h>
#include <math.h>

// Hausdorff, D=H=W=20, V=8000, batch 2. Exact integer squared-EDT.
// ONE kernel, 80 blocks: block = (transform t, z-plane z0).
// Front: per-warp UNROLLED batch of 40 coalesced LDGs (20 set-chunks + 20
// other-chunks, clamped indices -> full MLP), then 40 ballots -> two 250-word
// occupancy bitmaps in SMEM. Row bits via funnel shift; oo via bit test (no
// strided other-load). z-pass O(1) (clz/ffs); y/x passes tree-min in SMEM.
// Tail: per-block atomicMax + 80-arrival counter; last block finalizes.

#define INF_S 32000   // max legit squared distance = 3*19^2 = 1083
#define PAD   8

__device__ unsigned g_gmax[4 * PAD];   // per-transform max d2+1 (0 = none); zero-init
__device__ unsigned g_any[2 * PAD];    // any(mask A) per sample; zero-init
__device__ unsigned g_done = 0;

__global__ void __launch_bounds__(416, 1)
haus_plane(const float* __restrict__ predict,
           const float* __restrict__ targetp,
           float* __restrict__ out)
{
    __shared__ unsigned wS[256];       // set-mask occupancy words (flat v index)
    __shared__ unsigned wO[256];       // other-mask occupancy words
    __shared__ int F1[400];
    __shared__ int F2[400];
    __shared__ int sred;
    __shared__ int sany;

    const int b  = blockIdx.x;         // t*20 + z0
    const int t  = b / 20, z0 = b - t * 20;
    const int n  = t >> 1,  m  = t & 1;
    const float* setSrc = (m ? targetp : predict) + n * 8000;
    const float* othSrc = (m ? predict : targetp) + n * 8000;
    const int tid  = threadIdx.x;
    const int lane = tid & 31, warp = tid >> 5;   // 13 warps

    if (tid >= 250 && tid < 256) { wS[tid] = 0; wO[tid] = 0; }  // funnelshift guards
    if (tid == 0) { sred = 0; sany = 0; }

    // ---- front: batched loads (MLP ~40), then ballots ----
    float vs[20], vo[20];
    #pragma unroll
    for (int k = 0; k < 20; k++) {
        int j = warp + k * 13;                    // chunk id; max 259
        int jc = min(j, 249);                     // clamp keeps LDG in-bounds
        vs[k] = setSrc[jc * 32 + lane];
        vo[k] = othSrc[jc * 32 + lane];
    }
    unsigned anybit = 0;
    #pragma unroll
    for (int k = 0; k < 20; k++) {
        int j = warp + k * 13;
        // jnp.round == round-half-even == rintf
        unsigned bs = __ballot_sync(0xffffffffu, rintf(vs[k]) != 0.0f);
        unsigned bo = __ballot_sync(0xffffffffu, rintf(vo[k]) != 0.0f);
        if (j < 250) {
            anybit |= bs;
            if (lane == 0) { wS[j] = bs; wO[j] = bo; }
        }
    }
    if (lane == 0 && anybit) sany = 1;            // benign race
    __syncthreads();

    int x = 0, y = 0, oo = 0;
    if (tid < 400) {
        x = tid / 20; y = tid - x * 20;
        // own row's 20 set-occupancy bits: flat positions [20*tid, 20*tid+20)
        int p = tid * 20;
        unsigned bits = __funnelshift_r(wS[p >> 5], wS[(p >> 5) + 1], p & 31) & 0xFFFFFu;

        // z-pass at fixed z0: nearest set bit, O(1)
        int dist = 100;
        unsigned lo = bits & ((2u << z0) - 1u);
        if (lo) dist = z0 - (31 - __clz(lo));
        unsigned hi = bits >> z0;
        if (hi) dist = min(dist, __ffs(hi) - 1);
        F1[tid] = (dist <= 19) ? dist * dist : INF_S;

        // own-cell flags from the bitmaps (no strided gmem load)
        int pc = p + z0;                          // flat index of own cell
        int s  = (bits >> z0) & 1;
        int o  = (wO[pc >> 5] >> (pc & 31)) & 1;
        oo = o & (s ^ 1);                         // "other-only" point
    }
    __syncthreads();

    // ---- y-pass: F2(x,y) = min_yp F1(x,yp) + (y-yp)^2 (tree-min) ----
    if (tid < 400) {
        int c[20];
        const int base = x * 20;
        #pragma unroll
        for (int yp = 0; yp < 20; yp++) {
            int dy = y - yp;
            c[yp] = F1[base + yp] + dy * dy;
        }
        #pragma unroll
        for (int st = 1; st < 20; st <<= 1)
            #pragma unroll
            for (int i = 0; i + st < 20; i += (st << 1)) c[i] = min(c[i], c[i + st]);
        F2[tid] = c[0];
    }
    __syncthreads();

    // ---- x-pass + classification ----
    int enc = 0;                                  // best+1; 0 = none
    if (tid < 400) {
        int c[20];
        #pragma unroll
        for (int xp = 0; xp < 20; xp++) {
            int dx = x - xp;
            c[xp] = F2[xp * 20 + y] + dx * dx;
        }
        #pragma unroll
        for (int st = 1; st < 20; st <<= 1)
            #pragma unroll
            for (int i = 0; i + st < 20; i += (st << 1)) c[i] = min(c[i], c[i + st]);
        if (oo) enc = c[0] + 1;
    }
    enc = __reduce_max_sync(0xffffffffu, enc);
    if ((tid & 31) == 0 && enc) atomicMax(&sred, enc);
    __syncthreads();

    // ---- tail ----
    if (tid == 0) {
        if (sred) atomicMax(&g_gmax[t * PAD], (unsigned)sred);
        if (m == 0 && z0 == 0)                    // single writer per sample
            *(volatile unsigned*)&g_any[n * PAD] = (unsigned)sany;
        __threadfence();
        unsigned done = atomicAdd(&g_done, 1);
        if (done == 79) {
            __threadfence();
            volatile unsigned* vmax = (volatile unsigned*)g_gmax;
            volatile unsigned* vany = (volatile unsigned*)g_any;
            float sum = 0.0f;
            #pragma unroll
            for (int nn = 0; nn < 2; nn++) {
                int a2   = (int)vmax[(nn * 2 + 1) * PAD] - 1;  // A-only -> B (set=B)
                int b2   = (int)vmax[(nn * 2 + 0) * PAD] - 1;  // B-only -> A (set=A)
                int anyA = (int)vany[nn * PAD];
                float dA = 0.0f;
                if (a2 >= 0) dA = (a2 > 1083) ? 1e9f : sqrtf((float)a2) * 0.05f;
                float dB = 0.0f;
                if (b2 >= 0) dB = anyA ? ((b2 > 1083) ? 1e9f : sqrtf((float)b2) * 0.05f)
                                       : 999.0f;
                sum += fmaxf(dA, dB);
                vmax[(nn * 2 + 0) * PAD] = 0;
                vmax[(nn * 2 + 1) * PAD] = 0;
                vany[nn * PAD] = 0;
            }
            out[0] = sum * 0.5f;
            *(volatile unsigned*)&g_done = 0;     // restore static-init state
        }
    }
}

extern "C" void kernel_launch(void* const* d_in, const int* in_sizes, int n_in,
                              void* d_out, int out_size)
{
    const float* predict = (const float*)d_in[0];
    const float* targetp = (const float*)d_in[1];
    haus_plane<<<80, 416>>>(predict, targetp, (float*)d_out);
}

// round 13
// speedup vs baseline: 1.3082x; 1.1246x over previous
#include <cuda_runtime.h>
#include <math.h>

// Hausdorff, D=H=W=20, V=8000, batch 2. Exact integer squared-EDT.
// ONE kernel, 80 blocks: block = (transform t, z-plane z0).
// Front: fully coalesced volume sweep (5 float4/thread, 4 lines/warp-LDG,
// MLP=5) -> 4-bit nibbles in SMEM; each thread assembles its (x,y) row's
// 20 occupancy bits from 5 contiguous bytes. z-pass O(1) via clz/ffs;
// y/x passes tree-min in SMEM. Tail: per-block atomicMax + 80-arrival
// counter; last block finalizes + resets (graph-replay safe).

#define INF_S 32000   // max legit squared distance = 3*19^2 = 1083
#define PAD   8

__device__ unsigned g_gmax[4 * PAD];   // per-transform max d2+1 (0 = none); zero-init
__device__ unsigned g_any[2 * PAD];    // any(mask A) per sample; zero-init
__device__ unsigned g_done = 0;

__global__ void __launch_bounds__(416, 1)
haus_plane(const float* __restrict__ predict,
           const float* __restrict__ targetp,
           float* __restrict__ out)
{
    __shared__ unsigned char nib[2000];  // one 4-bit nibble per float4 of the volume
    __shared__ int F1[400];
    __shared__ int F2[400];
    __shared__ int sred;
    __shared__ int sany;

    const int b  = blockIdx.x;         // t*20 + z0
    const int t  = b / 20, z0 = b - t * 20;
    const int n  = t >> 1,  m  = t & 1;
    const float* setSrc = (m ? targetp : predict) + n * 8000;
    const float* othSrc = (m ? predict : targetp) + n * 8000;
    const int tid = threadIdx.x;

    if (tid == 0) { sred = 0; sany = 0; }

    // "other" mask at own cell (single strided LDG, latency overlapped)
    float ov = 0.0f;
    if (tid < 400) ov = othSrc[tid * 20 + z0];

    // ---- coalesced front: 5 float4s per thread (clamped -> unpredicated) ----
    const float4* src4 = (const float4*)setSrc;   // 2000 float4s
    float4 v[5];
    #pragma unroll
    for (int k = 0; k < 5; k++) {
        int f = tid + 416 * k;
        v[k] = src4[min(f, 1999)];
    }
    unsigned anyn = 0;
    #pragma unroll
    for (int k = 0; k < 5; k++) {
        int f = tid + 416 * k;
        // jnp.round == round-half-even == rintf
        unsigned nb = (rintf(v[k].x) != 0.0f ? 1u : 0u)
                    | (rintf(v[k].y) != 0.0f ? 2u : 0u)
                    | (rintf(v[k].z) != 0.0f ? 4u : 0u)
                    | (rintf(v[k].w) != 0.0f ? 8u : 0u);
        if (f < 2000) {
            nib[f] = (unsigned char)nb;
            anyn |= nb;
        }
    }
    int anyW = __any_sync(0xffffffffu, anyn != 0);
    if ((tid & 31) == 0 && anyW) sany = 1;       // benign race
    __syncthreads();

    int x = 0, y = 0, oo = 0;
    if (tid < 400) {
        x = tid / 20; y = tid - x * 20;
        // assemble own row's 20 bits from 5 contiguous nibbles
        const unsigned char* nb = &nib[tid * 5];
        unsigned bits = (unsigned)nb[0]
                      | ((unsigned)nb[1] << 4)
                      | ((unsigned)nb[2] << 8)
                      | ((unsigned)nb[3] << 12)
                      | ((unsigned)nb[4] << 16);

        // z-pass at fixed z0: nearest set bit, O(1)
        int dist = 100;
        unsigned lo = bits & ((2u << z0) - 1u);
        if (lo) dist = z0 - (31 - __clz(lo));
        unsigned hi = bits >> z0;
        if (hi) dist = min(dist, __ffs(hi) - 1);
        F1[tid] = (dist <= 19) ? dist * dist : INF_S;

        int s = (bits >> z0) & 1;
        oo = (rintf(ov) != 0.0f) & (s ^ 1);      // "other-only" point
    }
    __syncthreads();

    // ---- y-pass: F2(x,y) = min_yp F1(x,yp) + (y-yp)^2 (tree-min) ----
    if (tid < 400) {
        int c[20];
        const int base = x * 20;
        #pragma unroll
        for (int yp = 0; yp < 20; yp++) {
            int dy = y - yp;
            c[yp] = F1[base + yp] + dy * dy;
        }
        #pragma unroll
        for (int st = 1; st < 20; st <<= 1)
            #pragma unroll
            for (int i = 0; i + st < 20; i += (st << 1)) c[i] = min(c[i], c[i + st]);
        F2[tid] = c[0];
    }
    __syncthreads();

    // ---- x-pass + classification ----
    int enc = 0;                                  // best+1; 0 = none
    if (tid < 400) {
        int c[20];
        #pragma unroll
        for (int xp = 0; xp < 20; xp++) {
            int dx = x - xp;
            c[xp] = F2[xp * 20 + y] + dx * dx;
        }
        #pragma unroll
        for (int st = 1; st < 20; st <<= 1)
            #pragma unroll
            for (int i = 0; i + st < 20; i += (st << 1)) c[i] = min(c[i], c[i + st]);
        if (oo) enc = c[0] + 1;
    }
    enc = __reduce_max_sync(0xffffffffu, enc);
    if ((tid & 31) == 0 && enc) atomicMax(&sred, enc);
    __syncthreads();

    // ---- tail ----
    if (tid == 0) {
        if (sred) atomicMax(&g_gmax[t * PAD], (unsigned)sred);
        if (m == 0 && z0 == 0)                    // single writer per sample
            *(volatile unsigned*)&g_any[n * PAD] = (unsigned)sany;
        __threadfence();
        unsigned done = atomicAdd(&g_done, 1);
        if (done == 79) {
            __threadfence();
            volatile unsigned* vmax = (volatile unsigned*)g_gmax;
            volatile unsigned* vany = (volatile unsigned*)g_any;
            float sum = 0.0f;
            #pragma unroll
            for (int nn = 0; nn < 2; nn++) {
                int a2   = (int)vmax[(nn * 2 + 1) * PAD] - 1;  // A-only -> B (set=B)
                int b2   = (int)vmax[(nn * 2 + 0) * PAD] - 1;  // B-only -> A (set=A)
                int anyA = (int)vany[nn * PAD];
                float dA = 0.0f;
                if (a2 >= 0) dA = (a2 > 1083) ? 1e9f : sqrtf((float)a2) * 0.05f;
                float dB = 0.0f;
                if (b2 >= 0) dB = anyA ? ((b2 > 1083) ? 1e9f : sqrtf((float)b2) * 0.05f)
                                       : 999.0f;
                sum += fmaxf(dA, dB);
                vmax[(nn * 2 + 0) * PAD] = 0;
                vmax[(nn * 2 + 1) * PAD] = 0;
                vany[nn * PAD] = 0;
            }
            out[0] = sum * 0.5f;
            *(volatile unsigned*)&g_done = 0;     // restore static-init state
        }
    }
}

extern "C" void kernel_launch(void* const* d_in, const int* in_sizes, int n_in,
                              void* d_out, int out_size)
{
    const float* predict = (const float*)d_in[0];
    const float* targetp = (const float*)d_in[1];
    haus_plane<<<80, 416>>>(predict, targetp, (float*)d_out);
}

// round 14
// speedup vs baseline: 1.4301x; 1.0932x over previous
#include <cuda_runtime.h>
#include <math.h>

// Hausdorff, D=H=W=20, V=8000, batch 2. Exact integer squared-EDT.
// ONE kernel, 80 blocks: block = (transform t, z-plane z0), R7 front/body.
// Tail: per-sample ENCODED max slot (d2 in [1,1083] < 2000->999 < 3000->1e9,
// decode monotone, 0 = no contribution) -> ONE atomicMax per block, arrival
// via atom.acq_rel (no membar.gl anywhere). Last block decodes 2 slots.

#define INF_S 32000   // max legit squared distance = 3*19^2 = 1083
#define PAD   8

__device__ unsigned g_slot[2 * PAD];   // per-sample encoded haus max; zero-init
__device__ unsigned g_done = 0;

__device__ __forceinline__ unsigned atom_add_acq_rel(unsigned* p, unsigned v)
{
    unsigned old;
    asm volatile("atom.acq_rel.gpu.global.add.u32 %0, [%1], %2;"
                 : "=r"(old) : "l"(p), "r"(v) : "memory");
    return old;
}

__global__ void __launch_bounds__(416, 1)
haus_plane(const float* __restrict__ predict,
           const float* __restrict__ targetp,
           float* __restrict__ out)
{
    __shared__ int F1[400];
    __shared__ int F2[400];
    __shared__ int sred;
    __shared__ int sany;

    const int b  = blockIdx.x;         // t*20 + z0
    const int t  = b / 20, z0 = b - t * 20;
    const int n  = t >> 1,  m  = t & 1;
    const float* setSrc = (m ? targetp : predict) + n * 8000;
    const float* othSrc = (m ? predict : targetp) + n * 8000;
    const int tid = threadIdx.x;

    if (tid == 0) { sred = 0; sany = 0; }

    int x = 0, y = 0, oo = 0;
    unsigned rowbits = 0;
    if (tid < 400) {
        x = tid / 20; y = tid - x * 20;
        // Own (x,y) row over z: 20 contiguous floats = 5 x float4 (MLP=5).
        const float4* rp = (const float4*)(setSrc + tid * 20);
        float ov = othSrc[tid * 20 + z0];          // other mask at own cell
        #pragma unroll
        for (int q = 0; q < 5; q++) {
            float4 v = rp[q];
            // jnp.round == round-half-even == rintf
            rowbits |= (rintf(v.x) != 0.0f ? 1u : 0u) << (q * 4 + 0);
            rowbits |= (rintf(v.y) != 0.0f ? 1u : 0u) << (q * 4 + 1);
            rowbits |= (rintf(v.z) != 0.0f ? 1u : 0u) << (q * 4 + 2);
            rowbits |= (rintf(v.w) != 0.0f ? 1u : 0u) << (q * 4 + 3);
        }
        // z-pass at fixed z0: nearest set bit in own row, O(1).
        int dist = 100;
        unsigned lo = rowbits & ((2u << z0) - 1u);
        if (lo) dist = z0 - (31 - __clz(lo));
        unsigned hi = rowbits >> z0;
        if (hi) dist = min(dist, __ffs(hi) - 1);
        F1[tid] = (dist <= 19) ? dist * dist : INF_S;

        int s = (rowbits >> z0) & 1;
        oo = (rintf(ov) != 0.0f) & (s ^ 1);        // "other-only" point
    }
    // anyS: any set bit anywhere (400 rows cover the whole volume)
    int anyW = __any_sync(0xffffffffu, rowbits != 0);
    if ((tid & 31) == 0 && anyW) sany = 1;         // benign race
    __syncthreads();

    // ---- y-pass: F2(x,y) = min_yp F1(x,yp) + (y-yp)^2 ----
    if (tid < 400) {
        int c[20];
        const int base = x * 20;
        #pragma unroll
        for (int yp = 0; yp < 20; yp++) {
            int dy = y - yp;
            c[yp] = F1[base + yp] + dy * dy;
        }
        #pragma unroll
        for (int st = 1; st < 20; st <<= 1)
            #pragma unroll
            for (int i = 0; i + st < 20; i += (st << 1)) c[i] = min(c[i], c[i + st]);
        F2[tid] = c[0];
    }
    __syncthreads();

    // ---- x-pass + classification ----
    int enc = 0;                                   // d2 of other-only point; 0 = none
    if (tid < 400) {
        int c[20];
        #pragma unroll
        for (int xp = 0; xp < 20; xp++) {
            int dx = x - xp;
            c[xp] = F2[xp * 20 + y] + dx * dx;
        }
        #pragma unroll
        for (int st = 1; st < 20; st <<= 1)
            #pragma unroll
            for (int i = 0; i + st < 20; i += (st << 1)) c[i] = min(c[i], c[i + st]);
        if (oo) enc = c[0];                        // >= 1 always (cell not in set)
    }
    enc = __reduce_max_sync(0xffffffffu, enc);
    if ((tid & 31) == 0 && enc) atomicMax(&sred, enc);
    __syncthreads();

    // ---- tail: ONE encoded atomicMax + acq_rel arrival; last block decodes ----
    if (tid == 0) {
        // Encoding (monotone under decode):
        //   1..1083 -> sqrt(e)/20 ; 2000 -> 999 (A empty, distB case) ;
        //   3000 -> 1e9 (B empty, distA case) ; 0 -> no contribution.
        unsigned e = 0;
        if (sred) e = sany ? (unsigned)sred : (m ? 3000u : 2000u);
        if (e) atomicMax(&g_slot[n * PAD], e);
        unsigned done = atom_add_acq_rel(&g_done, 1);   // release: publishes the max
        if (done == 79) {                               // acq_rel: sees all slots
            float sum = 0.0f;
            #pragma unroll
            for (int nn = 0; nn < 2; nn++) {
                unsigned ev = *(volatile unsigned*)&g_slot[nn * PAD];
                float h = 0.0f;
                if (ev) h = (ev >= 3000u) ? 1e9f
                          : (ev >= 2000u) ? 999.0f
                          : sqrtf((float)ev) * 0.05f;
                sum += h;
                *(volatile unsigned*)&g_slot[nn * PAD] = 0;
            }
            out[0] = sum * 0.5f;
            *(volatile unsigned*)&g_done = 0;           // restore static-init state
        }
    }
}

extern "C" void kernel_launch(void* const* d_in, const int* in_sizes, int n_in,
                              void* d_out, int out_size)
{
    const float* predict = (const float*)d_in[0];
    const float* targetp = (const float*)d_in[1];
    haus_plane<<<80, 416>>>(predict, targetp, (float*)d_out);
}